// round 13
// baseline (speedup 1.0000x reference)
#include <cuda_runtime.h>
#include <math.h>

#define S   512
#define B   64
#define H   256
#define NH  4
#define NHH 1024      // NH*H
#define NCTA 128

typedef unsigned long long ull;

// ---------------- device globals (no runtime allocation allowed) ------------
__device__ float g_P[(size_t)S * H * B];       // [t][j][b]  : x@Wi.T
__device__ float g_gate[(size_t)S * B * NH];   // [t][b][nh] : sigmoid gates
// cand, ping-pong, packed {tag(hi32)=t, value(lo32)} per (j,b). Single 8B
// store/load is atomic -> tag rides with data, no fences needed.
__device__ ull g_cand[2][H * B];
__device__ float g_sel[B * NHH];               // hcat at t = len-1

// ---------------- init: reset cand tags to sentinel each replay -------------
__global__ void init_kernel() {
    int i = blockIdx.x * blockDim.x + threadIdx.x;      // 0 .. 16383
    const ull sent = 0xFFFFFFFF00000000ULL;
    g_cand[0][i] = sent;
    g_cand[1][i] = sent;
}

// ---------------- gate precompute: g = sigmoid(d - 3*nh) --------------------
__global__ __launch_bounds__(256)
void gate_kernel(const float* __restrict__ fix_src) {
    int t = blockIdx.x;
    int tid = threadIdx.x;          // b = tid>>2, nh = tid&3
    int b = tid >> 2, nh = tid & 3;
    float d = fix_src[b * S + t];
    g_gate[(size_t)t * (B * NH) + tid] = 1.0f / (1.0f + expf(3.0f * (float)nh - d));
}

// ---------------- P precompute: P[t][j][b] = emb[src[b,t]] . Wi[j,:] --------
__global__ __launch_bounds__(256, 2)
void p_kernel(const int* __restrict__ src, const float* __restrict__ emb,
              const float* __restrict__ Wi) {
    __shared__ float s_x[32][256];
    __shared__ int s_tok[32];
    const int t = blockIdx.x >> 1, bh = blockIdx.x & 1;
    const int tid = threadIdx.x;

    if (tid < 32) s_tok[tid] = src[(bh * 32 + tid) * S + t];
    __syncthreads();
    {
        int row = tid >> 3, seg = tid & 7;
        const float4* sp = (const float4*)(emb + (size_t)s_tok[row] * H) + seg * 8;
        float4* dp = (float4*)(&s_x[row][0]) + seg * 8;
        #pragma unroll
        for (int q = 0; q < 8; ++q) dp[q] = sp[q];
    }
    __syncthreads();

    float acc[32];
    #pragma unroll
    for (int m = 0; m < 32; ++m) acc[m] = 0.0f;
    const int j = tid;
    const float4* w4p = (const float4*)(Wi + (size_t)j * H);

    #pragma unroll 2
    for (int k4 = 0; k4 < 64; ++k4) {
        float4 wv = w4p[k4];
        #pragma unroll
        for (int m = 0; m < 32; ++m) {
            float4 xv = *(const float4*)&s_x[m][k4 * 4];
            acc[m] = fmaf(wv.x, xv.x, acc[m]);
            acc[m] = fmaf(wv.y, xv.y, acc[m]);
            acc[m] = fmaf(wv.z, xv.z, acc[m]);
            acc[m] = fmaf(wv.w, xv.w, acc[m]);
        }
    }
    float* out = g_P + (size_t)t * (H * B) + (size_t)j * B + bh * 32;
    #pragma unroll
    for (int m4 = 0; m4 < 8; ++m4)
        ((float4*)out)[m4] = make_float4(acc[m4 * 4], acc[m4 * 4 + 1],
                                         acc[m4 * 4 + 2], acc[m4 * 4 + 3]);
}

// ---------------- persistent recurrent kernel: 4j x 32b tiles ---------------
// 128 CTAs = 64 j-tiles x 2 b-groups (independent). 512 threads, 16 warps:
//   compute: warp w -> (ic = w&3: i-chunk of 64, jg = w>>2: local j), lane = b.
//   Per i: 1 LDS.32 cand + 1 broadcast LDS.128 weight + 4 FFMA (nh 0..3).
//   tail (tid<128): warp = local j, lane = b; owns z[4],h[4],cand state.
// Cross-CTA sync: tag in each 8B cand word (ping-pong); skew-safe.
__global__ __launch_bounds__(512, 1)
void rnn_kernel(const int* __restrict__ input_len,
                const float* __restrict__ bi, const float* __restrict__ bhb,
                const float* __restrict__ Wh) {
    extern __shared__ float sm[];
    float* s_W = sm;                  // [256][16]  q = jloc*4+nh   16 KB
    float* s_c = sm + 4096;           // [256][32]  [i][b]          32 KB
    float* s_y = sm + 4096 + 8192;    // [4 ic][16 q][32 b]          8 KB

    const int tid = threadIdx.x, cid = blockIdx.x;
    const int jt = cid >> 1, bt = cid & 1;
    const int w = tid >> 5, lane = tid & 31;
    const int jg = w >> 2, ic = w & 3;

    // load weights (coalesced on i): s_W[i*16+q] = Wh[(jt*4+q>>2)*1024 + (q&3)*256 + i]
    for (int u = tid; u < 4096; u += 512) {
        int i = u & 255, q = u >> 8;
        int jloc = q >> 2, nh = q & 3;
        s_W[i * 16 + q] = Wh[(size_t)(jt * 4 + jloc) * NHH + nh * H + i];
    }

    // tail state (tid < 128): warp = jloc, lane = b
    const int tj = tid >> 5;
    const int jglob = jt * 4 + tj;
    const int bglob = bt * 32 + lane;
    float bsum = 0.f, myc = 0.f;
    int mylen = 0;
    float z0 = 0.f, z1 = 0.f, z2 = 0.f, z3 = 0.f;
    float h0 = 0.f, h1 = 0.f, h2 = 0.f, h3 = 0.f;
    if (tid < 128) {
        bsum = bi[jglob] + bhb[jglob];
        mylen = input_len[bglob];
        // cand(0) = tanh(P[0] + bias), tag = 0
        myc = tanhf(__ldcg(&g_P[(size_t)jglob * B + bglob]) + bsum);
        __stcg(&g_cand[0][jglob * B + bglob], (ull)__float_as_uint(myc));
    }

    #pragma unroll 1
    for (int t = 0; t < S; ++t) {
        const int p = t & 1;
        const unsigned tagw = (unsigned)t;

        // ---- stage cand slice [256 i][32 b] into smem, tag-checked ----
        // warp w stages rows {w, w+16, ..., w+240}; lane = b (coalesced 8B).
        {
            const ull* gc = g_cand[p] + bt * 32 + lane;
            ull v[16];
            #pragma unroll
            for (int qq = 0; qq < 16; ++qq)
                v[qq] = __ldcg(gc + (w + 16 * qq) * B);
            #pragma unroll
            for (int qq = 0; qq < 16; ++qq) {
                if ((unsigned)(v[qq] >> 32) != tagw) {      // rare: not ready
                    const volatile ull* vp = gc + (w + 16 * qq) * B;
                    ull x;
                    do { x = *vp; } while ((unsigned)(x >> 32) != tagw);
                    v[qq] = x;
                }
                s_c[(w + 16 * qq) * 32 + lane] = __uint_as_float((unsigned)v[qq]);
            }
        }
        // tail prefetches (independent LDGs, overlap staging latency)
        float pnext = 0.0f;
        float4 g4 = make_float4(0.f, 0.f, 0.f, 0.f);
        if (tid < 128) {
            if (t < S - 1)
                pnext = __ldcg(&g_P[(size_t)(t + 1) * (H * B)
                                    + (size_t)jglob * B + bglob]);
            g4 = *(const float4*)&g_gate[(size_t)t * (B * NH) + bglob * 4];
        }
        __syncthreads();                  // s_c (and s_W, first iter) ready

        // ---- compute partial y for (jg, nh 0..3, b=lane) over i-chunk ic ----
        float a0 = 0.f, a1 = 0.f, a2 = 0.f, a3 = 0.f;
        {
            const float* cbase = s_c + (ic * 64) * 32 + lane;
            const float4* wbase = (const float4*)(s_W + (ic * 64) * 16 + jg * 4);
            #pragma unroll 16
            for (int i = 0; i < 64; ++i) {
                float cv = cbase[i * 32];            // conflict-free LDS.32
                float4 w4 = wbase[i * 4];            // broadcast LDS.128
                a0 = fmaf(w4.x, cv, a0);
                a1 = fmaf(w4.y, cv, a1);
                a2 = fmaf(w4.z, cv, a2);
                a3 = fmaf(w4.w, cv, a3);
            }
        }
        s_y[(ic * 16 + jg * 4 + 0) * 32 + lane] = a0;
        s_y[(ic * 16 + jg * 4 + 1) * 32 + lane] = a1;
        s_y[(ic * 16 + jg * 4 + 2) * 32 + lane] = a2;
        s_y[(ic * 16 + jg * 4 + 3) * 32 + lane] = a3;
        __syncthreads();                  // partials ready; also separates
                                          // compute(t) reads from stage(t+1)

        // ---- tail: reduce, gate, tanh, publish cand(t+1) ----
        if (tid < 128) {
            float y0 = 0.f, y1 = 0.f, y2 = 0.f, y3 = 0.f;
            #pragma unroll
            for (int kc = 0; kc < 4; ++kc) {
                y0 += s_y[(kc * 16 + tj * 4 + 0) * 32 + lane];
                y1 += s_y[(kc * 16 + tj * 4 + 1) * 32 + lane];
                y2 += s_y[(kc * 16 + tj * 4 + 2) * 32 + lane];
                y3 += s_y[(kc * 16 + tj * 4 + 3) * 32 + lane];
            }
            z0 = fmaf(g4.x, y0 - z0, z0);        // z' = z + g*(y - z)
            z1 = fmaf(g4.y, y1 - z1, z1);
            z2 = fmaf(g4.z, y2 - z2, z2);
            z3 = fmaf(g4.w, y3 - z3, z3);
            h0 = fmaf(g4.x, myc - h0, h0);       // h' = h + g*(cand - h)
            h1 = fmaf(g4.y, myc - h1, h1);
            h2 = fmaf(g4.z, myc - h2, h2);
            h3 = fmaf(g4.w, myc - h3, h3);

            if (t == mylen - 1) {
                g_sel[bglob * NHH + 0 * H + jglob] = h0;
                g_sel[bglob * NHH + 1 * H + jglob] = h1;
                g_sel[bglob * NHH + 2 * H + jglob] = h2;
                g_sel[bglob * NHH + 3 * H + jglob] = h3;
            }
            if (t < S - 1) {
                myc = tanhf(pnext + bsum + ((z0 + z1) + (z2 + z3)));
                ull pk = ((ull)(unsigned)(t + 1) << 32) |
                         (ull)__float_as_uint(myc);
                __stcg(&g_cand[(t + 1) & 1][jglob * B + bglob], pk);
            }
        }
    }
}

// ---------------- readout ---------------------------------------------------
__global__ __launch_bounds__(256)
void final_fc_kernel(const float* __restrict__ fc1_W,
                     const float* __restrict__ fc1_b,
                     const float* __restrict__ fc2_W,
                     const float* __restrict__ fc2_b,
                     float* __restrict__ out) {
    __shared__ float selsh[NHH];
    __shared__ float red0[H];
    __shared__ float red1[H];
    const int b = blockIdx.x;
    const int j = threadIdx.x;

    #pragma unroll
    for (int i = 0; i < NH; ++i)
        selsh[i * H + j] = g_sel[b * NHH + i * H + j];
    __syncthreads();

    float s = fc1_b[j];
    const float4* w = (const float4*)(fc1_W + (size_t)j * NHH);
    #pragma unroll 4
    for (int k4 = 0; k4 < NHH / 4; ++k4) {
        float4 wv = w[k4];
        float4 sv = *(const float4*)&selsh[k4 * 4];
        s = fmaf(wv.x, sv.x, s);
        s = fmaf(wv.y, sv.y, s);
        s = fmaf(wv.z, sv.z, s);
        s = fmaf(wv.w, sv.w, s);
    }
    s = tanhf(s);
    red0[j] = s * fc2_W[j];
    red1[j] = s * fc2_W[H + j];
    __syncthreads();

    for (int stride = 128; stride >= 1; stride >>= 1) {
        if (j < stride) {
            red0[j] += red0[j + stride];
            red1[j] += red1[j + stride];
        }
        __syncthreads();
    }
    if (j == 0) {
        out[b * 2 + 0] = red0[0] + fc2_b[0];
        out[b * 2 + 1] = red1[0] + fc2_b[1];
    }
}

// ---------------------------------------------------------------------------
extern "C" void kernel_launch(void* const* d_in, const int* in_sizes, int n_in,
                              void* d_out, int out_size) {
    const int*   src       = (const int*)  d_in[0];
    const int*   input_len = (const int*)  d_in[1];
    const float* fix_src   = (const float*)d_in[2];
    const float* emb_table = (const float*)d_in[3];
    const float* Wi        = (const float*)d_in[4];
    const float* bi        = (const float*)d_in[5];
    const float* Wh        = (const float*)d_in[6];
    const float* bh        = (const float*)d_in[7];
    const float* fc1_W     = (const float*)d_in[8];
    const float* fc1_b     = (const float*)d_in[9];
    const float* fc2_W     = (const float*)d_in[10];
    const float* fc2_b     = (const float*)d_in[11];
    float* out = (float*)d_out;

    const int rnn_smem = (4096 + 8192 + 2048) * 4;   // 57344 B
    cudaFuncSetAttribute(rnn_kernel,
                         cudaFuncAttributeMaxDynamicSharedMemorySize, rnn_smem);

    init_kernel<<<64, 256>>>();                 // clear cand tags (replay-safe)
    gate_kernel<<<S, 256>>>(fix_src);
    p_kernel<<<2 * S, 256>>>(src, emb_table, Wi);
    rnn_kernel<<<NCTA, 512, rnn_smem>>>(input_len, bi, bh, Wh);
    final_fc_kernel<<<B, 256>>>(fc1_W, fc1_b, fc2_W, fc2_b, out);
}

// round 14
// speedup vs baseline: 1.1931x; 1.1931x over previous
#include <cuda_runtime.h>
#include <math.h>

#define S   512
#define B   64
#define H   256
#define NH  4
#define NHH 1024      // NH*H
#define NCTA 256      // 2 CTAs per SM

typedef unsigned long long ull;

// ---------------- device globals (no runtime allocation allowed) ------------
__device__ float g_P[(size_t)S * H * B];       // [t][j][b]  : x@Wi.T
__device__ float g_gate[(size_t)S * B * NH];   // [t][b][nh] : sigmoid gates
// cand ring, depth 4, packed {tag(hi32)=t, value(lo32)} per (j,b). Single 8B
// store/load is atomic -> tag rides with data, no fences needed.
__device__ ull g_cand[4][H * B];
__device__ float g_sel[B * NHH];               // hcat at t = len-1

// ---------------- init: reset cand tags to sentinel each replay -------------
__global__ void init_kernel() {
    int i = blockIdx.x * blockDim.x + threadIdx.x;      // 0 .. 16383
    const ull sent = 0xFFFFFFFF00000000ULL;
    g_cand[0][i] = sent; g_cand[1][i] = sent;
    g_cand[2][i] = sent; g_cand[3][i] = sent;
}

// ---------------- fast tanh (MUFU-based, clamped) ---------------------------
__device__ __forceinline__ float fast_tanh(float x) {
    x = fminf(fmaxf(x, -15.0f), 15.0f);
    float e = __expf(-2.0f * x);
    return __fdividef(1.0f - e, 1.0f + e);
}

// ---------------- gate precompute: g = sigmoid(d - 3*nh) --------------------
__global__ __launch_bounds__(256)
void gate_kernel(const float* __restrict__ fix_src) {
    int t = blockIdx.x;
    int tid = threadIdx.x;          // b = tid>>2, nh = tid&3
    int b = tid >> 2, nh = tid & 3;
    float d = fix_src[b * S + t];
    g_gate[(size_t)t * (B * NH) + tid] = 1.0f / (1.0f + expf(3.0f * (float)nh - d));
}

// ---------------- P precompute: P[t][j][b] = emb[src[b,t]] . Wi[j,:] --------
__global__ __launch_bounds__(256, 2)
void p_kernel(const int* __restrict__ src, const float* __restrict__ emb,
              const float* __restrict__ Wi) {
    __shared__ float s_x[32][256];
    __shared__ int s_tok[32];
    const int t = blockIdx.x >> 1, bh = blockIdx.x & 1;
    const int tid = threadIdx.x;

    if (tid < 32) s_tok[tid] = src[(bh * 32 + tid) * S + t];
    __syncthreads();
    {
        int row = tid >> 3, seg = tid & 7;
        const float4* sp = (const float4*)(emb + (size_t)s_tok[row] * H) + seg * 8;
        float4* dp = (float4*)(&s_x[row][0]) + seg * 8;
        #pragma unroll
        for (int q = 0; q < 8; ++q) dp[q] = sp[q];
    }
    __syncthreads();

    float acc[32];
    #pragma unroll
    for (int m = 0; m < 32; ++m) acc[m] = 0.0f;
    const int j = tid;
    const float4* w4p = (const float4*)(Wi + (size_t)j * H);

    #pragma unroll 2
    for (int k4 = 0; k4 < 64; ++k4) {
        float4 wv = w4p[k4];
        #pragma unroll
        for (int m = 0; m < 32; ++m) {
            float4 xv = *(const float4*)&s_x[m][k4 * 4];
            acc[m] = fmaf(wv.x, xv.x, acc[m]);
            acc[m] = fmaf(wv.y, xv.y, acc[m]);
            acc[m] = fmaf(wv.z, xv.z, acc[m]);
            acc[m] = fmaf(wv.w, xv.w, acc[m]);
        }
    }
    float* out = g_P + (size_t)t * (H * B) + (size_t)j * B + bh * 32;
    #pragma unroll
    for (int m4 = 0; m4 < 8; ++m4)
        ((float4*)out)[m4] = make_float4(acc[m4 * 4], acc[m4 * 4 + 1],
                                         acc[m4 * 4 + 2], acc[m4 * 4 + 3]);
}

// ---------------- persistent recurrent kernel: 2 CTAs/SM, depth-4 ring ------
// 256 CTAs = 128 j-tiles x 2 b-groups. CTA owns j = {2jt, 2jt+1},
// b in [bt*32, bt*32+32). 256 threads: g = tid>>5 (8-way i-split of 32 rows),
// lane = local b. Each thread accumulates BOTH jl outputs (8 accumulators):
// per i, 1 coalesced LDG (32 lanes x 8B) + 2 broadcast LDS.128 + 8 FFMA.
// Cross-CTA sync: tag in each 8B cand word; ring depth 4 absorbs skew.
__global__ __launch_bounds__(256, 2)
void rnn_kernel(const int* __restrict__ input_len,
                const float* __restrict__ bi, const float* __restrict__ bhb,
                const float* __restrict__ Wh) {
    __shared__ float s_Wp[256 * 8];        // [i][jl][nh]  8 KB
    __shared__ float s_y[2][8][64][4];     // parity-buffered partials, 16 KB

    const int tid = threadIdx.x, cid = blockIdx.x;
    const int jt = cid >> 1, bt = cid & 1;
    const int g = tid >> 5, lane = tid & 31;
    const int jl = (tid >> 5) & 1;         // for tail threads (tid<64)
    const int j = jt * 2 + jl;
    const int b = bt * 32 + lane;

    // pack Wh: s_Wp[i*8 + jl*4 + nh] = Wh[2jt+jl][nh*256 + i]
    for (int u = tid; u < 2048; u += 256) {
        int i = u >> 3, ujl = (u >> 2) & 1, nh = u & 3;
        s_Wp[u] = Wh[(size_t)(jt * 2 + ujl) * NHH + nh * H + i];
    }

    float bsum = 0.f, myc = 0.f;
    int mylen = 0;
    if (tid < 64) {
        bsum = bi[j] + bhb[j];
        mylen = input_len[b];
        // cand(0) = tanh(P[0] + bias)   (z = 0); slot 0, tag 0
        myc = fast_tanh(__ldcg(&g_P[(size_t)j * B + b]) + bsum);
        __stcg(&g_cand[0][j * B + b], (ull)__float_as_uint(myc));
    }
    __syncthreads();                       // s_Wp visible CTA-wide

    float z0 = 0.f, z1 = 0.f, z2 = 0.f, z3 = 0.f;
    float h0 = 0.f, h1 = 0.f, h2 = 0.f, h3 = 0.f;

    #pragma unroll 1
    for (int t = 0; t < S; ++t) {
        const int p = t & 1;
        const unsigned tagw = (unsigned)t;

        // tail-thread prefetches (overlap the cand load stream)
        float pnext = 0.0f;
        float4 g4 = make_float4(0.f, 0.f, 0.f, 0.f);
        if (tid < 64) {
            if (t < S - 1)
                pnext = __ldcg(&g_P[(size_t)(t + 1) * (H * B)
                                    + (size_t)j * B + b]);
            g4 = *(const float4*)&g_gate[(size_t)t * (B * NH) + b * 4];
        }

        // partial y over our 32 cand rows, both jl at once; tag-checked loads
        float a0 = 0.f, a1 = 0.f, a2 = 0.f, a3 = 0.f;   // jl = 0
        float c0 = 0.f, c1 = 0.f, c2 = 0.f, c3 = 0.f;   // jl = 1
        const ull* cb = g_cand[t & 3] + (g << 5) * B + bt * 32 + lane;
        const float4* wb = (const float4*)&s_Wp[(g << 5) * 8];
        #pragma unroll 8
        for (int k = 0; k < 32; ++k) {
            ull v = __ldcg(cb + k * B);
            if ((unsigned)(v >> 32) != tagw) {           // rare: not ready yet
                const volatile ull* vp = cb + k * B;
                do { v = *vp; } while ((unsigned)(v >> 32) != tagw);
            }
            float cv = __uint_as_float((unsigned)v);
            float4 wA = wb[k * 2];          // warp-broadcast LDS.128
            float4 wB = wb[k * 2 + 1];
            a0 = fmaf(wA.x, cv, a0); a1 = fmaf(wA.y, cv, a1);
            a2 = fmaf(wA.z, cv, a2); a3 = fmaf(wA.w, cv, a3);
            c0 = fmaf(wB.x, cv, c0); c1 = fmaf(wB.y, cv, c1);
            c2 = fmaf(wB.z, cv, c2); c3 = fmaf(wB.w, cv, c3);
        }
        *(float4*)&s_y[p][g][lane][0]      = make_float4(a0, a1, a2, a3);
        *(float4*)&s_y[p][g][32 + lane][0] = make_float4(c0, c1, c2, c3);
        __syncthreads();    // partials of step t visible; parity buffer keeps
                            // step t+1 writers off this slot

        if (tid < 64) {
            float y0 = 0.f, y1 = 0.f, y2 = 0.f, y3 = 0.f;
            #pragma unroll
            for (int gg = 0; gg < 8; ++gg) {
                float4 yv = *(const float4*)&s_y[p][gg][jl * 32 + lane][0];
                y0 += yv.x; y1 += yv.y; y2 += yv.z; y3 += yv.w;
            }
            z0 = fmaf(g4.x, y0 - z0, z0);        // z' = z + g*(y - z)
            z1 = fmaf(g4.y, y1 - z1, z1);
            z2 = fmaf(g4.z, y2 - z2, z2);
            z3 = fmaf(g4.w, y3 - z3, z3);
            h0 = fmaf(g4.x, myc - h0, h0);       // h' = h + g*(cand - h)
            h1 = fmaf(g4.y, myc - h1, h1);
            h2 = fmaf(g4.z, myc - h2, h2);
            h3 = fmaf(g4.w, myc - h3, h3);

            if (t == mylen - 1) {
                g_sel[b * NHH + 0 * H + j] = h0;
                g_sel[b * NHH + 1 * H + j] = h1;
                g_sel[b * NHH + 2 * H + j] = h2;
                g_sel[b * NHH + 3 * H + j] = h3;
            }
            if (t < S - 1) {
                myc = fast_tanh(pnext + bsum + ((z0 + z1) + (z2 + z3)));
                ull pk = ((ull)(unsigned)(t + 1) << 32) |
                         (ull)__float_as_uint(myc);
                __stcg(&g_cand[(t + 1) & 3][j * B + b], pk);
            }
        }
    }
}

// ---------------- readout ---------------------------------------------------
__global__ __launch_bounds__(256)
void final_fc_kernel(const float* __restrict__ fc1_W,
                     const float* __restrict__ fc1_b,
                     const float* __restrict__ fc2_W,
                     const float* __restrict__ fc2_b,
                     float* __restrict__ out) {
    __shared__ float selsh[NHH];
    __shared__ float red0[H];
    __shared__ float red1[H];
    const int b = blockIdx.x;
    const int j = threadIdx.x;

    #pragma unroll
    for (int i = 0; i < NH; ++i)
        selsh[i * H + j] = g_sel[b * NHH + i * H + j];
    __syncthreads();

    float s = fc1_b[j];
    const float4* w = (const float4*)(fc1_W + (size_t)j * NHH);
    #pragma unroll 4
    for (int k4 = 0; k4 < NHH / 4; ++k4) {
        float4 wv = w[k4];
        float4 sv = *(const float4*)&selsh[k4 * 4];
        s = fmaf(wv.x, sv.x, s);
        s = fmaf(wv.y, sv.y, s);
        s = fmaf(wv.z, sv.z, s);
        s = fmaf(wv.w, sv.w, s);
    }
    s = tanhf(s);
    red0[j] = s * fc2_W[j];
    red1[j] = s * fc2_W[H + j];
    __syncthreads();

    for (int stride = 128; stride >= 1; stride >>= 1) {
        if (j < stride) {
            red0[j] += red0[j + stride];
            red1[j] += red1[j + stride];
        }
        __syncthreads();
    }
    if (j == 0) {
        out[b * 2 + 0] = red0[0] + fc2_b[0];
        out[b * 2 + 1] = red1[0] + fc2_b[1];
    }
}

// ---------------------------------------------------------------------------
extern "C" void kernel_launch(void* const* d_in, const int* in_sizes, int n_in,
                              void* d_out, int out_size) {
    const int*   src       = (const int*)  d_in[0];
    const int*   input_len = (const int*)  d_in[1];
    const float* fix_src   = (const float*)d_in[2];
    const float* emb_table = (const float*)d_in[3];
    const float* Wi        = (const float*)d_in[4];
    const float* bi        = (const float*)d_in[5];
    const float* Wh        = (const float*)d_in[6];
    const float* bh        = (const float*)d_in[7];
    const float* fc1_W     = (const float*)d_in[8];
    const float* fc1_b     = (const float*)d_in[9];
    const float* fc2_W     = (const float*)d_in[10];
    const float* fc2_b     = (const float*)d_in[11];
    float* out = (float*)d_out;

    init_kernel<<<256, 256>>>();                // clear cand tags (replay-safe)
    gate_kernel<<<S, 256>>>(fix_src);
    p_kernel<<<2 * S, 256>>>(src, emb_table, Wi);
    rnn_kernel<<<NCTA, 256>>>(input_len, bi, bh, Wh);
    final_fc_kernel<<<B, 256>>>(fc1_W, fc1_b, fc2_W, fc2_b, out);
}

// round 15
// speedup vs baseline: 1.4626x; 1.2259x over previous
#include <cuda_runtime.h>
#include <math.h>

#define S   512
#define B   64
#define H   256
#define NH  4
#define NHH 1024      // NH*H
#define NCTA 128

typedef unsigned long long ull;

// ---------------- device globals (no runtime allocation allowed) ------------
__device__ float g_P[(size_t)S * H * B];       // [t][j][b]  : x@Wi.T
__device__ float g_gate[(size_t)S * B * NH];   // [t][b][nh] : sigmoid gates
// cand ring, depth 4, packed {tag(hi32)=t, value(lo32)} per (j,b). Single 8B
// store/load is atomic -> tag rides with data, no fences needed.
__device__ ull g_cand[4][H * B];
__device__ float g_sel[B * NHH];               // hcat at t = len-1

// ---------------- init: reset cand tags to sentinel each replay -------------
__global__ void init_kernel() {
    int i = blockIdx.x * blockDim.x + threadIdx.x;      // 0 .. 16383
    const ull sent = 0xFFFFFFFF00000000ULL;
    g_cand[0][i] = sent; g_cand[1][i] = sent;
    g_cand[2][i] = sent; g_cand[3][i] = sent;
}

// ---------------- fast tanh (MUFU-based, clamped) ---------------------------
__device__ __forceinline__ float fast_tanh(float x) {
    x = fminf(fmaxf(x, -15.0f), 15.0f);
    float e = __expf(-2.0f * x);
    return __fdividef(1.0f - e, 1.0f + e);
}

// ---------------- gate precompute: g = sigmoid(d - 3*nh) --------------------
__global__ __launch_bounds__(256)
void gate_kernel(const float* __restrict__ fix_src) {
    int t = blockIdx.x;
    int tid = threadIdx.x;          // b = tid>>2, nh = tid&3
    int b = tid >> 2, nh = tid & 3;
    float d = fix_src[b * S + t];
    g_gate[(size_t)t * (B * NH) + tid] = 1.0f / (1.0f + expf(3.0f * (float)nh - d));
}

// ---------------- P precompute: P[t][j][b] = emb[src[b,t]] . Wi[j,:] --------
__global__ __launch_bounds__(256, 2)
void p_kernel(const int* __restrict__ src, const float* __restrict__ emb,
              const float* __restrict__ Wi) {
    __shared__ float s_x[32][256];
    __shared__ int s_tok[32];
    const int t = blockIdx.x >> 1, bh = blockIdx.x & 1;
    const int tid = threadIdx.x;

    if (tid < 32) s_tok[tid] = src[(bh * 32 + tid) * S + t];
    __syncthreads();
    {
        int row = tid >> 3, seg = tid & 7;
        const float4* sp = (const float4*)(emb + (size_t)s_tok[row] * H) + seg * 8;
        float4* dp = (float4*)(&s_x[row][0]) + seg * 8;
        #pragma unroll
        for (int q = 0; q < 8; ++q) dp[q] = sp[q];
    }
    __syncthreads();

    float acc[32];
    #pragma unroll
    for (int m = 0; m < 32; ++m) acc[m] = 0.0f;
    const int j = tid;
    const float4* w4p = (const float4*)(Wi + (size_t)j * H);

    #pragma unroll 2
    for (int k4 = 0; k4 < 64; ++k4) {
        float4 wv = w4p[k4];
        #pragma unroll
        for (int m = 0; m < 32; ++m) {
            float4 xv = *(const float4*)&s_x[m][k4 * 4];
            acc[m] = fmaf(wv.x, xv.x, acc[m]);
            acc[m] = fmaf(wv.y, xv.y, acc[m]);
            acc[m] = fmaf(wv.z, xv.z, acc[m]);
            acc[m] = fmaf(wv.w, xv.w, acc[m]);
        }
    }
    float* out = g_P + (size_t)t * (H * B) + (size_t)j * B + bh * 32;
    #pragma unroll
    for (int m4 = 0; m4 < 8; ++m4)
        ((float4*)out)[m4] = make_float4(acc[m4 * 4], acc[m4 * 4 + 1],
                                         acc[m4 * 4 + 2], acc[m4 * 4 + 3]);
}

// ---------------- persistent recurrent kernel: 1024 thr, depth-4 ring -------
// 128 CTAs, CTA c owns output columns j = {2c, 2c+1}, full batch b=0..63.
// 1024 threads: g = tid>>6 (16-way i-split, 16 cand rows each), b = tid&63.
// Each thread accumulates BOTH jl outputs (8 accumulators): per i,
// 1 coalesced LDG.64 (tagged word) + 2 broadcast LDS.128 + 8 FFMA.
// Cross-CTA sync: tag in each 8B cand word; ring depth 4 absorbs skew.
__global__ __launch_bounds__(1024, 1)
void rnn_kernel(const int* __restrict__ input_len,
                const float* __restrict__ bi, const float* __restrict__ bhb,
                const float* __restrict__ Wh) {
    extern __shared__ float sm[];
    float* s_Wp = sm;                 // [i][jl][nh]  2048 floats, 8 KB
    float* s_y  = sm + 2048;          // [2][16][128][4]  16384 floats, 64 KB

    const int tid = threadIdx.x, cid = blockIdx.x;
    const int g = tid >> 6, b = tid & 63;
    const int jl = (tid >> 6) & 1;         // for tail threads (tid<128)
    const int j = cid * 2 + jl;

    // pack Wh: s_Wp[i*8 + jl*4 + nh] = Wh[2c+jl][nh*256 + i]
    for (int u = tid; u < 2048; u += 1024) {
        int i = u >> 3, ujl = (u >> 2) & 1, nh = u & 3;
        s_Wp[u] = Wh[(size_t)(cid * 2 + ujl) * NHH + nh * H + i];
    }

    float bsum = 0.f, myc = 0.f;
    int mylen = 0;
    if (tid < 128) {
        bsum = bi[j] + bhb[j];
        mylen = input_len[b];
        // cand(0) = tanh(P[0] + bias)   (z = 0); slot 0, tag 0
        myc = fast_tanh(__ldcg(&g_P[(size_t)j * B + b]) + bsum);
        __stcg(&g_cand[0][j * B + b], (ull)__float_as_uint(myc));
    }
    __syncthreads();                       // s_Wp visible CTA-wide

    float z0 = 0.f, z1 = 0.f, z2 = 0.f, z3 = 0.f;
    float h0 = 0.f, h1 = 0.f, h2 = 0.f, h3 = 0.f;

    #pragma unroll 1
    for (int t = 0; t < S; ++t) {
        const int p = t & 1;
        const unsigned tagw = (unsigned)t;

        // tail-thread prefetches (overlap the cand load stream)
        float pnext = 0.0f;
        float4 g4 = make_float4(0.f, 0.f, 0.f, 0.f);
        if (tid < 128) {
            if (t < S - 1)
                pnext = __ldcg(&g_P[(size_t)(t + 1) * (H * B)
                                    + (size_t)j * B + b]);
            g4 = *(const float4*)&g_gate[(size_t)t * (B * NH) + b * 4];
        }

        // partial y over our 16 cand rows, both jl at once; tag-checked loads
        float a0 = 0.f, a1 = 0.f, a2 = 0.f, a3 = 0.f;   // jl = 0
        float c0 = 0.f, c1 = 0.f, c2 = 0.f, c3 = 0.f;   // jl = 1
        const ull* cb = g_cand[t & 3] + (g << 4) * B + b;
        const float4* wb = (const float4*)&s_Wp[(g << 4) * 8];
        #pragma unroll 8
        for (int k = 0; k < 16; ++k) {
            ull v = __ldcg(cb + k * B);
            if ((unsigned)(v >> 32) != tagw) {           // rare: not ready yet
                const volatile ull* vp = cb + k * B;
                do { v = *vp; } while ((unsigned)(v >> 32) != tagw);
            }
            float cv = __uint_as_float((unsigned)v);
            float4 wA = wb[k * 2];          // warp-broadcast LDS.128
            float4 wB = wb[k * 2 + 1];
            a0 = fmaf(wA.x, cv, a0); a1 = fmaf(wA.y, cv, a1);
            a2 = fmaf(wA.z, cv, a2); a3 = fmaf(wA.w, cv, a3);
            c0 = fmaf(wB.x, cv, c0); c1 = fmaf(wB.y, cv, c1);
            c2 = fmaf(wB.z, cv, c2); c3 = fmaf(wB.w, cv, c3);
        }
        *(float4*)&s_y[((p * 16 + g) * 128 + b) * 4]      =
            make_float4(a0, a1, a2, a3);
        *(float4*)&s_y[((p * 16 + g) * 128 + 64 + b) * 4] =
            make_float4(c0, c1, c2, c3);
        __syncthreads();    // partials of step t visible; parity buffer keeps
                            // step t+1 writers off this slot

        if (tid < 128) {
            float y0 = 0.f, y1 = 0.f, y2 = 0.f, y3 = 0.f;
            #pragma unroll
            for (int gg = 0; gg < 16; ++gg) {
                float4 yv = *(const float4*)
                    &s_y[((p * 16 + gg) * 128 + jl * 64 + b) * 4];
                y0 += yv.x; y1 += yv.y; y2 += yv.z; y3 += yv.w;
            }
            z0 = fmaf(g4.x, y0 - z0, z0);        // z' = z + g*(y - z)
            z1 = fmaf(g4.y, y1 - z1, z1);
            z2 = fmaf(g4.z, y2 - z2, z2);
            z3 = fmaf(g4.w, y3 - z3, z3);
            h0 = fmaf(g4.x, myc - h0, h0);       // h' = h + g*(cand - h)
            h1 = fmaf(g4.y, myc - h1, h1);
            h2 = fmaf(g4.z, myc - h2, h2);
            h3 = fmaf(g4.w, myc - h3, h3);

            if (t == mylen - 1) {
                g_sel[b * NHH + 0 * H + j] = h0;
                g_sel[b * NHH + 1 * H + j] = h1;
                g_sel[b * NHH + 2 * H + j] = h2;
                g_sel[b * NHH + 3 * H + j] = h3;
            }
            if (t < S - 1) {
                myc = fast_tanh(pnext + bsum + ((z0 + z1) + (z2 + z3)));
                ull pk = ((ull)(unsigned)(t + 1) << 32) |
                         (ull)__float_as_uint(myc);
                __stcg(&g_cand[(t + 1) & 3][j * B + b], pk);
            }
        }
    }
}

// ---------------- readout ---------------------------------------------------
__global__ __launch_bounds__(256)
void final_fc_kernel(const float* __restrict__ fc1_W,
                     const float* __restrict__ fc1_b,
                     const float* __restrict__ fc2_W,
                     const float* __restrict__ fc2_b,
                     float* __restrict__ out) {
    __shared__ float selsh[NHH];
    __shared__ float red0[H];
    __shared__ float red1[H];
    const int b = blockIdx.x;
    const int j = threadIdx.x;

    #pragma unroll
    for (int i = 0; i < NH; ++i)
        selsh[i * H + j] = g_sel[b * NHH + i * H + j];
    __syncthreads();

    float s = fc1_b[j];
    const float4* w = (const float4*)(fc1_W + (size_t)j * NHH);
    #pragma unroll 4
    for (int k4 = 0; k4 < NHH / 4; ++k4) {
        float4 wv = w[k4];
        float4 sv = *(const float4*)&selsh[k4 * 4];
        s = fmaf(wv.x, sv.x, s);
        s = fmaf(wv.y, sv.y, s);
        s = fmaf(wv.z, sv.z, s);
        s = fmaf(wv.w, sv.w, s);
    }
    s = tanhf(s);
    red0[j] = s * fc2_W[j];
    red1[j] = s * fc2_W[H + j];
    __syncthreads();

    for (int stride = 128; stride >= 1; stride >>= 1) {
        if (j < stride) {
            red0[j] += red0[j + stride];
            red1[j] += red1[j + stride];
        }
        __syncthreads();
    }
    if (j == 0) {
        out[b * 2 + 0] = red0[0] + fc2_b[0];
        out[b * 2 + 1] = red1[0] + fc2_b[1];
    }
}

// ---------------------------------------------------------------------------
extern "C" void kernel_launch(void* const* d_in, const int* in_sizes, int n_in,
                              void* d_out, int out_size) {
    const int*   src       = (const int*)  d_in[0];
    const int*   input_len = (const int*)  d_in[1];
    const float* fix_src   = (const float*)d_in[2];
    const float* emb_table = (const float*)d_in[3];
    const float* Wi        = (const float*)d_in[4];
    const float* bi        = (const float*)d_in[5];
    const float* Wh        = (const float*)d_in[6];
    const float* bh        = (const float*)d_in[7];
    const float* fc1_W     = (const float*)d_in[8];
    const float* fc1_b     = (const float*)d_in[9];
    const float* fc2_W     = (const float*)d_in[10];
    const float* fc2_b     = (const float*)d_in[11];
    float* out = (float*)d_out;

    const int rnn_smem = (2048 + 16384) * 4;   // 73728 B
    cudaFuncSetAttribute(rnn_kernel,
                         cudaFuncAttributeMaxDynamicSharedMemorySize, rnn_smem);

    init_kernel<<<64, 256>>>();                 // clear cand tags (replay-safe)
    gate_kernel<<<S, 256>>>(fix_src);
    p_kernel<<<2 * S, 256>>>(src, emb_table, Wi);
    rnn_kernel<<<NCTA, 1024, rnn_smem>>>(input_len, bi, bh, Wh);
    final_fc_kernel<<<B, 256>>>(fc1_W, fc1_b, fc2_W, fc2_b, out);
}